// round 4
// baseline (speedup 1.0000x reference)
#include <cuda_runtime.h>
#include <math_constants.h>

#define NDIM  512
#define NKNOT 32
#define NDATA 65536

#define DT   32            // dims per block tile (one warp-width)
#define TPB  256           // 32 dims x 8 rows per iteration
#define RPB  512           // rows per block

// Knot tables, knot-major within dim: g_P[k*NDIM + d] = {xx,yy}; g_D = dd.
__device__ float2 g_P [NKNOT * NDIM];
__device__ float  g_D [NKNOT * NDIM];
// Level-2 pivots per (quadrant, dim): {xx[8q+1], xx[8q+3], xx[8q+5], 0}
__device__ float4 g_P2[4 * NDIM];
// Even-index knot positions: g_XE[j*NDIM + d] = xx[2j]
__device__ float  g_XE[(NKNOT / 2) * NDIM];
// Level-1 pivots per dim: {xx[7], xx[15], xx[23], +inf}
__device__ float4 g_P1[NDIM];

// ---------------------------------------------------------------------------
__global__ void prep_kernel(const float* __restrict__ params) {
    int d = blockIdx.x * blockDim.x + threadIdx.x;
    if (d >= NDIM) return;

    const float* logdx    = params + 2 * NDIM + d * (NKNOT - 1);
    const float* logdy    = params + 2 * NDIM + NDIM * (NKNOT - 1) + d * (NKNOT - 1);
    const float* logderiv = params + 2 * NDIM + 2 * NDIM * (NKNOT - 1) + d * NKNOT;

    float xx[NKNOT], yy[NKNOT], dd[NKNOT];
    xx[0] = params[d];
    yy[0] = params[NDIM + d];
    dd[0] = expf(logderiv[0]);
    #pragma unroll
    for (int k = 1; k < NKNOT; k++) {
        xx[k] = xx[k - 1] + expf(logdx[k - 1]);
        yy[k] = yy[k - 1] + expf(logdy[k - 1]);
        dd[k] = expf(logderiv[k]);
    }

    #pragma unroll
    for (int k = 0; k < NKNOT; k++) {
        g_P[k * NDIM + d] = make_float2(xx[k], yy[k]);
        g_D[k * NDIM + d] = dd[k];
    }
    #pragma unroll
    for (int q = 0; q < 4; q++)
        g_P2[q * NDIM + d] = make_float4(xx[8 * q + 1], xx[8 * q + 3], xx[8 * q + 5], 0.0f);
    #pragma unroll
    for (int j = 0; j < NKNOT / 2; j++)
        g_XE[j * NDIM + d] = xx[2 * j];

    g_P1[d] = make_float4(xx[7], xx[15], xx[23], CUDART_INF_F);
}

// ---------------------------------------------------------------------------
// Main kernel: 32-dim tile, 512-row slab. 4-ary tournament search (L1 pivots
// in registers, L2 = LDS.128, L3 = LDS.32), gathers split as 2xLDS.64 +
// 2xLDS.32 (24B/elem). All smem traffic bank-conflict-free.
// ---------------------------------------------------------------------------
__global__ __launch_bounds__(TPB, 6) void spline_kernel(
    const float* __restrict__ x, float* __restrict__ out)
{
    __shared__ float2 sP [NKNOT * DT];          // 8 KB
    __shared__ float  sD [NKNOT * DT];          // 4 KB
    __shared__ float4 sP2[4 * DT];              // 2 KB
    __shared__ float  sXE[(NKNOT / 2) * DT];    // 2 KB

    const int dbase = blockIdx.x * DT;
    const int tid = threadIdx.x;

    // Coalesced table-tile fills.
    #pragma unroll
    for (int i = tid; i < NKNOT * DT; i += TPB) {
        int g = (i >> 5) * NDIM + dbase + (i & 31);
        sP[i] = g_P[g];
        sD[i] = g_D[g];
    }
    if (tid < 4 * DT)
        sP2[tid] = g_P2[(tid >> 5) * NDIM + dbase + (tid & 31)];
    #pragma unroll
    for (int i = tid; i < (NKNOT / 2) * DT; i += TPB)
        sXE[i] = g_XE[(i >> 5) * NDIM + dbase + (i & 31)];

    const int d  = tid & 31;
    const int rl = tid >> 5;                     // 0..7
    const int r0 = blockIdx.y * RPB;

    // Per-thread L1 pivots (hoisted; L2-cached global read).
    const float4 p1 = g_P1[dbase + d];

    __syncthreads();

    const float xxlast = sP[(NKNOT - 1) * DT + d].x;

    float* __restrict__ yout  = out;
    float* __restrict__ ldout = out + NDATA * NDIM;

    unsigned off = (unsigned)(r0 + rl) * NDIM + dbase + d;
    const unsigned step = (TPB / DT) * NDIM;

    #pragma unroll 4
    for (int rr = rl; rr < RPB; rr += TPB / DT, off += step) {
        const float xv = __ldg(x + off);

        // --- 4-ary tournament lower bound: base = min(#knots < xv, 31) ---
        const int q = (p1.x < xv) + (p1.y < xv) + (p1.z < xv);
        const float4 p2 = sP2[q * DT + d];
        const int t = (p2.x < xv) + (p2.y < xv) + (p2.z < xv);
        const int j = 4 * q + t;
        const int base = 2 * j + (sXE[j * DT + d] < xv);

        const bool sel0 = (base == 0);       // index == 0     (low tail)
        const bool selN = (xxlast < xv);     // index == NKNOT (high tail)

        const int ic = base > 1 ? base : 1;  // clip(index, 1, 31)
        const int lo = (ic - 1) * DT + d;
        const float2 plo = sP[lo];
        const float2 phi = sP[lo + DT];      // imm offset +256B
        const float  dl  = sD[lo];
        const float  dh  = sD[lo + DT];      // imm offset +128B

        const float x_lo = plo.x, y_lo = plo.y;
        const float x_hi = phi.x, y_hi = phi.y;

        // --- rational-quadratic mid branch (tail lanes overwritten below) ---
        const float inv_dx = __fdividef(1.0f, x_hi - x_lo);
        const float xi     = (xv - x_lo) * inv_dx;
        const float dy     = y_hi - y_lo;
        const float s      = dy * inv_dx;
        const float omxi   = 1.0f - xi;
        const float xi1    = xi * omxi;
        const float xi2    = xi * xi;
        const float den    = fmaf(dh + dl - 2.0f * s, xi1, s);   // > 0 always
        const float inv_den = __fdividef(1.0f, den);
        float yv = fmaf(dy * fmaf(s, xi2, dl * xi1), inv_den, y_lo);
        const float num = fmaf(dh, xi2, fmaf(2.0f * s, xi1, dl * omxi * omxi));
        const float rs  = s * inv_den;
        float larg = rs * rs * num;          // 2log(s)+log(num)-2log(den)

        if (selN) { yv = fmaf(xv - x_hi, dh, y_hi); larg = dh; }
        if (sel0) { yv = fmaf(xv - x_lo, dl, y_lo); larg = dl; }

        yout[off]  = yv;
        ldout[off] = __logf(larg);
    }
}

extern "C" void kernel_launch(void* const* d_in, const int* in_sizes, int n_in,
                              void* d_out, int out_size) {
    const float* x      = (const float*)d_in[0];
    const float* params = (const float*)d_in[1];
    float* out = (float*)d_out;

    prep_kernel<<<(NDIM + 255) / 256, 256>>>(params);

    dim3 grid(NDIM / DT, NDATA / RPB);
    spline_kernel<<<grid, TPB>>>(x, out);
}

// round 5
// speedup vs baseline: 1.1869x; 1.1869x over previous
#include <cuda_runtime.h>
#include <math_constants.h>

#define NDIM  512
#define NKNOT 32
#define NDATA 65536
#define NBIN  (NKNOT + 1)     // 33: tail-low + 31 interior + tail-high

#define DT   32               // dims per block tile (one warp-width)
#define TPB  256              // 32 dims x 8 rows per iteration
#define RPB  256              // rows per block
#define TAILW 64.0f           // tail fake-bin width (power of 2 -> exact xi)

// Bin coefficient records, bin-major: g_RA/g_RB[b*NDIM + d]
//   RA = {t0 = -x_lo/dx, inv_dx, y_lo, dy}
//   RB = {s, c = dh+dl-2s, dl, dh}
__device__ float4 g_RA[NBIN * NDIM];
__device__ float4 g_RB[NBIN * NDIM];
// Level-2 pivots per (quadrant, dim): {xx[8q+1], xx[8q+3], xx[8q+5], 0}
__device__ float4 g_P2[4 * NDIM];
// Even-index knot positions: g_XE[j*NDIM + d] = xx[2j]
__device__ float  g_XE[(NKNOT / 2) * NDIM];
// Level-1 pivots per dim: {xx[7], xx[15], xx[23], xx[31]}
__device__ float4 g_P1[NDIM];

// ---------------------------------------------------------------------------
__global__ void prep_kernel(const float* __restrict__ params) {
    int d = blockIdx.x * blockDim.x + threadIdx.x;
    if (d >= NDIM) return;

    const float* logdx    = params + 2 * NDIM + d * (NKNOT - 1);
    const float* logdy    = params + 2 * NDIM + NDIM * (NKNOT - 1) + d * (NKNOT - 1);
    const float* logderiv = params + 2 * NDIM + 2 * NDIM * (NKNOT - 1) + d * NKNOT;

    float xx[NKNOT], yy[NKNOT], dd[NKNOT];
    xx[0] = params[d];
    yy[0] = params[NDIM + d];
    dd[0] = expf(logderiv[0]);
    #pragma unroll
    for (int k = 1; k < NKNOT; k++) {
        xx[k] = xx[k - 1] + expf(logdx[k - 1]);
        yy[k] = yy[k - 1] + expf(logdy[k - 1]);
        dd[k] = expf(logderiv[k]);
    }

    // Bin 0: low tail as exact-linear RQ bin [xx0 - 64, xx0], dl=dh=s=dd0.
    {
        const float invw = 1.0f / TAILW;
        g_RA[d] = make_float4(1.0f - xx[0] * invw, invw,
                              yy[0] - TAILW * dd[0], TAILW * dd[0]);
        g_RB[d] = make_float4(dd[0], 0.0f, dd[0], dd[0]);
    }
    // Bins 1..31: real intervals [xx[b-1], xx[b]].
    #pragma unroll
    for (int b = 1; b < NKNOT; b++) {
        const float dx = xx[b] - xx[b - 1];
        const float inv_dx = 1.0f / dx;
        const float dy = yy[b] - yy[b - 1];
        const float s  = dy * inv_dx;
        g_RA[b * NDIM + d] = make_float4(-xx[b - 1] * inv_dx, inv_dx, yy[b - 1], dy);
        g_RB[b * NDIM + d] = make_float4(s, dd[b] + dd[b - 1] - 2.0f * s,
                                         dd[b - 1], dd[b]);
    }
    // Bin 32: high tail [xx31, xx31 + 64], dl=dh=s=dd31.
    {
        const float invw = 1.0f / TAILW;
        g_RA[NKNOT * NDIM + d] = make_float4(-xx[NKNOT - 1] * invw, invw,
                                             yy[NKNOT - 1], TAILW * dd[NKNOT - 1]);
        g_RB[NKNOT * NDIM + d] = make_float4(dd[NKNOT - 1], 0.0f,
                                             dd[NKNOT - 1], dd[NKNOT - 1]);
    }

    #pragma unroll
    for (int q = 0; q < 4; q++)
        g_P2[q * NDIM + d] = make_float4(xx[8 * q + 1], xx[8 * q + 3], xx[8 * q + 5], 0.0f);
    #pragma unroll
    for (int j = 0; j < NKNOT / 2; j++)
        g_XE[j * NDIM + d] = xx[2 * j];

    g_P1[d] = make_float4(xx[7], xx[15], xx[23], xx[NKNOT - 1]);
}

// ---------------------------------------------------------------------------
// Main kernel: 32-dim tile, 256-row slab. Branchless: search returns bin
// b = #{knots < x} in [0,32]; tails are exact-linear RQ bins, so one unified
// formula, no selects. Gathers = 2x LDS.128, bank-conflict-free.
// ---------------------------------------------------------------------------
__global__ __launch_bounds__(TPB, 6) void spline_kernel(
    const float* __restrict__ x, float* __restrict__ out)
{
    __shared__ float4 sRA[NBIN * DT];           // 16.5 KB
    __shared__ float4 sRB[NBIN * DT];           // 16.5 KB
    __shared__ float4 sP2[4 * DT];              // 2 KB
    __shared__ float  sXE[(NKNOT / 2) * DT];    // 2 KB

    const int dbase = blockIdx.x * DT;
    const int tid = threadIdx.x;

    #pragma unroll
    for (int i = tid; i < NBIN * DT; i += TPB) {
        int g = (i >> 5) * NDIM + dbase + (i & 31);
        sRA[i] = g_RA[g];
        sRB[i] = g_RB[g];
    }
    if (tid < 4 * DT)
        sP2[tid] = g_P2[(tid >> 5) * NDIM + dbase + (tid & 31)];
    #pragma unroll
    for (int i = tid; i < (NKNOT / 2) * DT; i += TPB)
        sXE[i] = g_XE[(i >> 5) * NDIM + dbase + (i & 31)];

    const int d  = tid & 31;
    const int rl = tid >> 5;                     // 0..7
    const int r0 = blockIdx.y * RPB;

    // Per-thread L1 pivots (hoisted; p1.w = xx[31]).
    const float4 p1 = g_P1[dbase + d];

    __syncthreads();

    float* __restrict__ yout  = out;
    float* __restrict__ ldout = out + NDATA * NDIM;

    unsigned off = (unsigned)(r0 + rl) * NDIM + dbase + d;
    const unsigned step = (TPB / DT) * NDIM;

    #pragma unroll 4
    for (int rr = rl; rr < RPB; rr += TPB / DT, off += step) {
        const float xv = __ldg(x + off);

        // --- tournament: b = #{knots < xv} in [0, 32] ---
        const int q = (p1.x < xv) + (p1.y < xv) + (p1.z < xv);
        const float4 p2 = sP2[q * DT + d];
        const int t = (p2.x < xv) + (p2.y < xv) + (p2.z < xv);
        const int j = 4 * q + t;
        const int b = 2 * j + (sXE[j * DT + d] < xv) + (p1.w < xv);

        const int rec = b * DT + d;
        const float4 rA = sRA[rec];   // {t0, inv_dx, y_lo, dy}
        const float4 rB = sRB[rec];   // {s, c, dl, dh}

        // --- unified rational-quadratic evaluation (tails exact-linear) ---
        const float xi    = fmaf(xv, rA.y, rA.x);
        const float xi2   = xi * xi;
        const float omxi  = 1.0f - xi;
        const float xi1   = xi * omxi;
        const float u2    = xi1 + xi1;
        const float den   = fmaf(rB.y, xi1, rB.x);          // s + c*xi1 > 0
        const float rden  = __fdividef(1.0f, den);
        const float p     = fmaf(rB.x, xi2, rB.z * xi1);    // s*xi2 + dl*xi1
        const float dyr   = rA.w * rden;
        const float yv    = fmaf(p, dyr, rA.z);
        const float omxi2 = omxi * omxi;
        const float num   = fmaf(rB.w, xi2, fmaf(rB.x, u2, rB.z * omxi2));
        const float rs    = rB.x * rden;                    // s/den
        const float larg  = rs * rs * num;                  // s^2*num/den^2

        yout[off]  = yv;
        ldout[off] = __logf(larg);
    }
}

extern "C" void kernel_launch(void* const* d_in, const int* in_sizes, int n_in,
                              void* d_out, int out_size) {
    const float* x      = (const float*)d_in[0];
    const float* params = (const float*)d_in[1];
    float* out = (float*)d_out;

    prep_kernel<<<(NDIM + 255) / 256, 256>>>(params);

    dim3 grid(NDIM / DT, NDATA / RPB);
    spline_kernel<<<grid, TPB>>>(x, out);
}

// round 6
// speedup vs baseline: 1.2134x; 1.0223x over previous
#include <cuda_runtime.h>
#include <math_constants.h>

#define NDIM  512
#define NKNOT 32
#define NDATA 65536
#define NBIN  (NKNOT + 1)     // 33: tail-low + 31 interior + tail-high

#define DT   32               // dims per block tile (one warp-width)
#define TPB  256              // 32 dims x 8 rows per iteration
#define RPB  256              // rows per block
#define TAILW 64.0f           // tail fake-bin width (power of 2 -> exact xi)

// Bin coefficient records, bin-major: g_RA/g_RB[b*NDIM + d]
//   RA = {t0 = -x_lo/dx, inv_dx, a2, a1}   (P = a2 xi^2 + a1 xi + a0)
//   RB = {a0, c, s, e1 = 2(s - dl)}        (den = -c xi^2 + c xi + s,
//                                           num =  c xi^2 + e1 xi + dl)
__device__ float4 g_RA[NBIN * NDIM];
__device__ float4 g_RB[NBIN * NDIM];
// Level-2 pivots per (quadrant, dim): {xx[8q+1], xx[8q+3], xx[8q+5], 0}
__device__ float4 g_P2[4 * NDIM];
// Even-index knot positions: g_XE[j*NDIM + d] = xx[2j]
__device__ float  g_XE[(NKNOT / 2) * NDIM];
// Level-1 pivots per dim: {xx[7], xx[15], xx[23], xx[31]}
__device__ float4 g_P1[NDIM];

// ---------------------------------------------------------------------------
__global__ void prep_kernel(const float* __restrict__ params) {
    int d = blockIdx.x * blockDim.x + threadIdx.x;
    if (d >= NDIM) return;

    const float* logdx    = params + 2 * NDIM + d * (NKNOT - 1);
    const float* logdy    = params + 2 * NDIM + NDIM * (NKNOT - 1) + d * (NKNOT - 1);
    const float* logderiv = params + 2 * NDIM + 2 * NDIM * (NKNOT - 1) + d * NKNOT;

    float xx[NKNOT], yy[NKNOT], dd[NKNOT];
    xx[0] = params[d];
    yy[0] = params[NDIM + d];
    dd[0] = expf(logderiv[0]);
    #pragma unroll
    for (int k = 1; k < NKNOT; k++) {
        xx[k] = xx[k - 1] + expf(logdx[k - 1]);
        yy[k] = yy[k - 1] + expf(logdy[k - 1]);
        dd[k] = expf(logderiv[k]);
    }

    // Emit one bin record: interval [x_lo, x_lo + dx], values y_lo/dy, derivs dl/dh.
    auto emit = [&](int b, float x_lo, float dx, float y_lo, float dy,
                    float dl, float dh) {
        const float inv_dx = 1.0f / dx;
        const float s = dy * inv_dx;
        const float c = dh + dl - 2.0f * s;
        const float a0 = y_lo * s;
        const float a1 = y_lo * c + dy * dl;
        const float a2 = -y_lo * c + dy * (s - dl);
        g_RA[b * NDIM + d] = make_float4(-x_lo * inv_dx, inv_dx, a2, a1);
        g_RB[b * NDIM + d] = make_float4(a0, c, s, 2.0f * (s - dl));
    };

    // Bin 0: low tail as exact-linear RQ bin [xx0 - TAILW, xx0].
    emit(0, xx[0] - TAILW, TAILW, yy[0] - TAILW * dd[0], TAILW * dd[0], dd[0], dd[0]);
    // Bins 1..31: real intervals.
    #pragma unroll
    for (int b = 1; b < NKNOT; b++)
        emit(b, xx[b - 1], xx[b] - xx[b - 1], yy[b - 1], yy[b] - yy[b - 1],
             dd[b - 1], dd[b]);
    // Bin 32: high tail [xx31, xx31 + TAILW].
    emit(NKNOT, xx[NKNOT - 1], TAILW, yy[NKNOT - 1], TAILW * dd[NKNOT - 1],
         dd[NKNOT - 1], dd[NKNOT - 1]);

    #pragma unroll
    for (int q = 0; q < 4; q++)
        g_P2[q * NDIM + d] = make_float4(xx[8 * q + 1], xx[8 * q + 3], xx[8 * q + 5], 0.0f);
    #pragma unroll
    for (int j = 0; j < NKNOT / 2; j++)
        g_XE[j * NDIM + d] = xx[2 * j];

    g_P1[d] = make_float4(xx[7], xx[15], xx[23], xx[NKNOT - 1]);
}

// ---------------------------------------------------------------------------
// Main kernel: 32-dim tile, 256-row slab. Branchless bin search in [0,32];
// unified Horner rational-quadratic evaluation. Gathers = 2x LDS.128,
// bank-conflict-free for any data-dependent bin.
// ---------------------------------------------------------------------------
__global__ __launch_bounds__(TPB, 6) void spline_kernel(
    const float* __restrict__ x, float* __restrict__ out)
{
    __shared__ float4 sRA[NBIN * DT];           // 16.5 KB
    __shared__ float4 sRB[NBIN * DT];           // 16.5 KB
    __shared__ float4 sP2[4 * DT];              // 2 KB
    __shared__ float  sXE[(NKNOT / 2) * DT];    // 2 KB

    const int dbase = blockIdx.x * DT;
    const int tid = threadIdx.x;

    #pragma unroll
    for (int i = tid; i < NBIN * DT; i += TPB) {
        int g = (i >> 5) * NDIM + dbase + (i & 31);
        sRA[i] = g_RA[g];
        sRB[i] = g_RB[g];
    }
    if (tid < 4 * DT)
        sP2[tid] = g_P2[(tid >> 5) * NDIM + dbase + (tid & 31)];
    #pragma unroll
    for (int i = tid; i < (NKNOT / 2) * DT; i += TPB)
        sXE[i] = g_XE[(i >> 5) * NDIM + dbase + (i & 31)];

    const int d  = tid & 31;
    const int rl = tid >> 5;                     // 0..7
    const int r0 = blockIdx.y * RPB;

    // Per-thread L1 pivots (hoisted; p1.w = xx[31]).
    const float4 p1 = g_P1[dbase + d];

    __syncthreads();

    float* __restrict__ yout  = out;
    float* __restrict__ ldout = out + NDATA * NDIM;

    unsigned off = (unsigned)(r0 + rl) * NDIM + dbase + d;
    const unsigned step = (TPB / DT) * NDIM;

    #pragma unroll 4
    for (int rr = rl; rr < RPB; rr += TPB / DT, off += step) {
        const float xv = __ldg(x + off);

        // --- tournament: b = #{knots < xv} in [0, 32] ---
        const int q = (p1.x < xv) + (p1.y < xv) + (p1.z < xv);
        const float4 p2 = sP2[q * DT + d];
        const int t = (p2.x < xv) + (p2.y < xv) + (p2.z < xv);
        const int j = 4 * q + t;
        const int b = 2 * j + (sXE[j * DT + d] < xv) + (p1.w < xv);

        const int rec = b * DT + d;
        const float4 rA = sRA[rec];   // {t0, inv_dx, a2, a1}
        const float4 rB = sRB[rec];   // {a0, c, s, e1}

        // --- Horner rational-quadratic evaluation ---
        const float xi   = fmaf(xv, rA.y, rA.x);
        const float P    = fmaf(fmaf(rA.z, xi, rA.w), xi, rB.x);
        const float den  = fmaf(fmaf(-rB.y, xi, rB.y), xi, rB.z);  // > 0 always
        const float rden = __fdividef(1.0f, den);
        const float yv   = P * rden;
        const float dl   = fmaf(-0.5f, rB.w, rB.z);                // dl = s - e1/2
        const float num  = fmaf(fmaf(rB.y, xi, rB.w), xi, dl);
        const float rs   = rB.z * rden;                            // s / den
        const float larg = rs * rs * num;                          // s^2 num / den^2

        yout[off]  = yv;
        ldout[off] = __logf(larg);
    }
}

extern "C" void kernel_launch(void* const* d_in, const int* in_sizes, int n_in,
                              void* d_out, int out_size) {
    const float* x      = (const float*)d_in[0];
    const float* params = (const float*)d_in[1];
    float* out = (float*)d_out;

    prep_kernel<<<(NDIM + 255) / 256, 256>>>(params);

    dim3 grid(NDIM / DT, NDATA / RPB);
    spline_kernel<<<grid, TPB>>>(x, out);
}

// round 7
// speedup vs baseline: 1.2216x; 1.0068x over previous
#include <cuda_runtime.h>
#include <math_constants.h>

#define NDIM  512
#define NKNOT 32
#define NDATA 65536
#define NBIN  (NKNOT + 1)     // 33: tail-low + 31 interior + tail-high

#define DT   32               // dims per block tile (one warp-width)
#define TPB  512              // 32 dims x 16 rows per iteration
#define RPB  256              // rows per block
#define TAILW 64.0f           // tail fake-bin width (power of 2 -> exact xi)

// Bin coefficient records, bin-major: g_RA/g_RB[b*NDIM + d]
//   RA = {t0 = -x_lo/dx, inv_dx, a2, a1}   (P = a2 xi^2 + a1 xi + a0)
//   RB = {a0, c, s, e1 = 2(s - dl)}        (den = -c xi^2 + c xi + s,
//                                           num =  c xi^2 + e1 xi + dl)
__device__ float4 g_RA[NBIN * NDIM];
__device__ float4 g_RB[NBIN * NDIM];
// Level-2 pivots per (quadrant, dim): {xx[8q+1], xx[8q+3], xx[8q+5], 0}
__device__ float4 g_P2[4 * NDIM];
// Even-index knot positions: g_XE[j*NDIM + d] = xx[2j]
__device__ float  g_XE[(NKNOT / 2) * NDIM];
// Level-1 pivots per dim: {xx[7], xx[15], xx[23], xx[31]}
__device__ float4 g_P1[NDIM];

// ---------------------------------------------------------------------------
__global__ void prep_kernel(const float* __restrict__ params) {
    int d = blockIdx.x * blockDim.x + threadIdx.x;
    if (d >= NDIM) return;

    const float* logdx    = params + 2 * NDIM + d * (NKNOT - 1);
    const float* logdy    = params + 2 * NDIM + NDIM * (NKNOT - 1) + d * (NKNOT - 1);
    const float* logderiv = params + 2 * NDIM + 2 * NDIM * (NKNOT - 1) + d * NKNOT;

    float xx[NKNOT], yy[NKNOT], dd[NKNOT];
    xx[0] = params[d];
    yy[0] = params[NDIM + d];
    dd[0] = expf(logderiv[0]);
    #pragma unroll
    for (int k = 1; k < NKNOT; k++) {
        xx[k] = xx[k - 1] + expf(logdx[k - 1]);
        yy[k] = yy[k - 1] + expf(logdy[k - 1]);
        dd[k] = expf(logderiv[k]);
    }

    // Emit one bin record: interval [x_lo, x_lo + dx], values y_lo/dy, derivs dl/dh.
    auto emit = [&](int b, float x_lo, float dx, float y_lo, float dy,
                    float dl, float dh) {
        const float inv_dx = 1.0f / dx;
        const float s = dy * inv_dx;
        const float c = dh + dl - 2.0f * s;
        const float a0 = y_lo * s;
        const float a1 = y_lo * c + dy * dl;
        const float a2 = -y_lo * c + dy * (s - dl);
        g_RA[b * NDIM + d] = make_float4(-x_lo * inv_dx, inv_dx, a2, a1);
        g_RB[b * NDIM + d] = make_float4(a0, c, s, 2.0f * (s - dl));
    };

    // Bin 0: low tail as exact-linear RQ bin [xx0 - TAILW, xx0].
    emit(0, xx[0] - TAILW, TAILW, yy[0] - TAILW * dd[0], TAILW * dd[0], dd[0], dd[0]);
    // Bins 1..31: real intervals.
    #pragma unroll
    for (int b = 1; b < NKNOT; b++)
        emit(b, xx[b - 1], xx[b] - xx[b - 1], yy[b - 1], yy[b] - yy[b - 1],
             dd[b - 1], dd[b]);
    // Bin 32: high tail [xx31, xx31 + TAILW].
    emit(NKNOT, xx[NKNOT - 1], TAILW, yy[NKNOT - 1], TAILW * dd[NKNOT - 1],
         dd[NKNOT - 1], dd[NKNOT - 1]);

    #pragma unroll
    for (int q = 0; q < 4; q++)
        g_P2[q * NDIM + d] = make_float4(xx[8 * q + 1], xx[8 * q + 3], xx[8 * q + 5], 0.0f);
    #pragma unroll
    for (int j = 0; j < NKNOT / 2; j++)
        g_XE[j * NDIM + d] = xx[2 * j];

    g_P1[d] = make_float4(xx[7], xx[15], xx[23], xx[NKNOT - 1]);
}

// ---------------------------------------------------------------------------
// Main kernel: 32-dim tile, 256-row slab, 512 threads (16 row-lanes).
// Branchless bin search in [0,32]; unified Horner rational-quadratic
// evaluation. Gathers = 2x LDS.128, bank-conflict-free for any bin.
// 3 blocks/SM -> 48 warps (100% theoretical occupancy).
// ---------------------------------------------------------------------------
__global__ __launch_bounds__(TPB, 3) void spline_kernel(
    const float* __restrict__ x, float* __restrict__ out)
{
    __shared__ float4 sRA[NBIN * DT];           // 16.5 KB
    __shared__ float4 sRB[NBIN * DT];           // 16.5 KB
    __shared__ float4 sP2[4 * DT];              // 2 KB
    __shared__ float  sXE[(NKNOT / 2) * DT];    // 2 KB

    const int dbase = blockIdx.x * DT;
    const int tid = threadIdx.x;

    #pragma unroll
    for (int i = tid; i < NBIN * DT; i += TPB) {
        int g = (i >> 5) * NDIM + dbase + (i & 31);
        sRA[i] = g_RA[g];
        sRB[i] = g_RB[g];
    }
    if (tid < 4 * DT)
        sP2[tid] = g_P2[(tid >> 5) * NDIM + dbase + (tid & 31)];
    if (tid < (NKNOT / 2) * DT)
        sXE[tid] = g_XE[(tid >> 5) * NDIM + dbase + (tid & 31)];

    const int d  = tid & 31;
    const int rl = tid >> 5;                     // 0..15
    const int r0 = blockIdx.y * RPB;

    // Per-thread L1 pivots (hoisted; p1.w = xx[31]).
    const float4 p1 = g_P1[dbase + d];

    __syncthreads();

    float* __restrict__ yout  = out;
    float* __restrict__ ldout = out + NDATA * NDIM;

    unsigned off = (unsigned)(r0 + rl) * NDIM + dbase + d;
    const unsigned step = (TPB / DT) * NDIM;

    #pragma unroll 4
    for (int rr = rl; rr < RPB; rr += TPB / DT, off += step) {
        const float xv = __ldg(x + off);

        // --- tournament: b = #{knots < xv} in [0, 32] ---
        const int q = (p1.x < xv) + (p1.y < xv) + (p1.z < xv);
        const float4 p2 = sP2[q * DT + d];
        const int t = (p2.x < xv) + (p2.y < xv) + (p2.z < xv);
        const int j = 4 * q + t;
        const int b = 2 * j + (sXE[j * DT + d] < xv) + (p1.w < xv);

        const int rec = b * DT + d;
        const float4 rA = sRA[rec];   // {t0, inv_dx, a2, a1}
        const float4 rB = sRB[rec];   // {a0, c, s, e1}

        // --- Horner rational-quadratic evaluation ---
        const float xi   = fmaf(xv, rA.y, rA.x);
        const float P    = fmaf(fmaf(rA.z, xi, rA.w), xi, rB.x);
        const float den  = fmaf(fmaf(-rB.y, xi, rB.y), xi, rB.z);  // > 0 always
        const float rden = __fdividef(1.0f, den);
        const float yv   = P * rden;
        const float dl   = fmaf(-0.5f, rB.w, rB.z);                // dl = s - e1/2
        const float num  = fmaf(fmaf(rB.y, xi, rB.w), xi, dl);
        const float rs   = rB.z * rden;                            // s / den
        const float larg = rs * rs * num;                          // s^2 num / den^2

        yout[off]  = yv;
        ldout[off] = __logf(larg);
    }
}

extern "C" void kernel_launch(void* const* d_in, const int* in_sizes, int n_in,
                              void* d_out, int out_size) {
    const float* x      = (const float*)d_in[0];
    const float* params = (const float*)d_in[1];
    float* out = (float*)d_out;

    prep_kernel<<<(NDIM + 255) / 256, 256>>>(params);

    dim3 grid(NDIM / DT, NDATA / RPB);
    spline_kernel<<<grid, TPB>>>(x, out);
}